// round 15
// baseline (speedup 1.0000x reference)
#include <cuda_runtime.h>
#include <math.h>

#define NBG 16          // b*g
#define CGc 8           // channels per group
#define SPL 262144      // 64*64*64
#define PLANE 4096      // 64*64

// ---------------- device scratch (static, no runtime alloc) ----------------
__device__ float g_pool[NBG*CGc*192];
__device__ float g_a[NBG*CGc*192];
__device__ float g_x2raw[(size_t)NBG*CGc*SPL];   // 134 MB raw conv output
__device__ float g_tsum[NBG*CGc];
__device__ float g_tsq[NBG*CGc];
__device__ float g_bnsum[CGc];
__device__ float g_bnsq[CGc];
__device__ float g_gnscale[NBG*CGc];
__device__ float g_gnshift[NBG*CGc];
__device__ float g_bnscale[CGc];
__device__ float g_bnshift[CGc];
__device__ float g_x2sum[NBG*CGc];
__device__ float g_x11[CGc];
__device__ float g_x21[NBG*CGc];

__device__ __forceinline__ unsigned f2tf32(float v) {
    unsigned u;
    asm("cvt.rna.tf32.f32 %0, %1;" : "=r"(u) : "f"(v));
    return u;
}

// ---------------- K0: zero accumulators ----------------
__global__ void k_zero() {
    int i = blockIdx.x * 256 + threadIdx.x;
    if (i < NBG*CGc*192) g_pool[i] = 0.f;
    if (i < NBG*CGc) { g_tsum[i] = 0.f; g_tsq[i] = 0.f; g_x2sum[i] = 0.f; }
    if (i < CGc) { g_bnsum[i] = 0.f; g_bnsq[i] = 0.f; }
}

// ---------------- K1: directional pools ----------------
__global__ void __launch_bounds__(256) k_pool(const float* __restrict__ x) {
    int nc = blockIdx.x;
    int q  = blockIdx.y;                 // d chunk 0..3
    const float* base = x + (size_t)nc * SPL;
    int t  = threadIdx.x;
    int w_ = t & 63, hb = t >> 6;        // hb 0..3

    __shared__ float s_h[16], s_w[64], s_d[64];
    if (t < 16) s_h[t] = 0.f;
    if (t < 64) { s_w[t] = 0.f; s_d[t] = 0.f; }
    __syncthreads();

    float hpart[16];
#pragma unroll
    for (int k = 0; k < 16; k++) hpart[k] = 0.f;
    float sdp = 0.f;

    for (int dd = 0; dd < 16; dd++) {
        int d = q * 16 + dd;
        const float* pl = base + d * PLANE;
        float ps = 0.f;
#pragma unroll
        for (int k = 0; k < 16; k++) {
            float v = pl[(hb + 4*k) * 64 + w_];
            ps += v;
            hpart[k] += v;
        }
        sdp += ps;
#pragma unroll
        for (int o = 16; o > 0; o >>= 1) ps += __shfl_down_sync(0xffffffffu, ps, o);
        if ((t & 31) == 0) atomicAdd(&s_h[dd], ps);
    }
#pragma unroll
    for (int k = 0; k < 16; k++) {
        float v = hpart[k];
#pragma unroll
        for (int o = 16; o > 0; o >>= 1) v += __shfl_down_sync(0xffffffffu, v, o);
        if ((t & 31) == 0) atomicAdd(&s_w[hb + 4*k], v);
    }
    atomicAdd(&s_d[w_], sdp);
    __syncthreads();

    float* outp = g_pool + nc * 192;
    if (t < 16) outp[q * 16 + t] = s_h[t];            // exclusive per (nc,q)
    if (t < 64) {
        atomicAdd(&outp[64  + t], s_w[t]);
        atomicAdd(&outp[128 + t], s_d[t]);
    }
}

// ---------------- K2: conv1(1x1x1) + BN1(train) + ReLU + sigmoid ----------------
__global__ void __launch_bounds__(1024) k_excite(const float* __restrict__ w1,
                                                 const float* __restrict__ b1,
                                                 const float* __restrict__ bn1g,
                                                 const float* __restrict__ bn1b) {
    __shared__ float s_w1[64], s_sum[8], s_sq[8], s_scale[8], s_shift[8];
    int t = threadIdx.x;
    if (t < 64) s_w1[t] = w1[t];
    if (t < 8) { s_sum[t] = 0.f; s_sq[t] = 0.f; }
    __syncthreads();

    int o = t >> 7;       // output channel 0..7
    int j = t & 127;      // position within o-group
    float bo = b1[o];
    float lsum = 0.f, lsq = 0.f;

    for (int i = 0; i < 24; i++) {
        int idx = j + (i << 7);           // 0..3071  -> (n,s)
        int n = idx / 192, s = idx - n * 192;
        float dot = 0.f;
#pragma unroll
        for (int ic = 0; ic < 8; ic++)
            dot += s_w1[o*8 + ic] * g_pool[(n*8 + ic)*192 + s];
        float h = bo + dot * (1.f / 4096.f);
        g_a[(n*8 + o)*192 + s] = h;       // stage hwd
        lsum += h; lsq += h * h;
    }
#pragma unroll
    for (int oo = 16; oo > 0; oo >>= 1) {
        lsum += __shfl_down_sync(0xffffffffu, lsum, oo);
        lsq  += __shfl_down_sync(0xffffffffu, lsq,  oo);
    }
    if ((t & 31) == 0) { atomicAdd(&s_sum[o], lsum); atomicAdd(&s_sq[o], lsq); }
    __syncthreads();
    if (t < 8) {
        float m   = s_sum[t] * (1.f / 3072.f);
        float var = s_sq[t]  * (1.f / 3072.f) - m * m;
        float rs  = rsqrtf(var + 1e-5f);
        float sc  = bn1g[t] * rs;
        s_scale[t] = sc;
        s_shift[t] = bn1b[t] - m * sc;
    }
    __syncthreads();
    float sc = s_scale[o], sh = s_shift[o];
    for (int i = 0; i < 24; i++) {
        int idx = j + (i << 7);
        int n = idx / 192, s = idx - n * 192;
        int e = (n*8 + o)*192 + s;
        float h = g_a[e];
        float y = fmaxf(fmaf(sc, h, sh), 0.f);
        g_a[e] = 1.f / (1.f + expf(-y));
    }
}

// ---------------- K3: 3x3x3 conv via tf32 m16n8k8 mma.sync + BN3/GN stats ----------------
// CTA tile: z=4, y=4, w=64. SINGLE pass: K=8 covers all 8 input channels per MMA.
// Per warp: 8 m16-tiles x 27 taps = 216 MMAs (4 LDS + 1 HMMA each).
#define SZT 6
#define SYT 6
#define SWT 68
#define ZSTR (SYT*SWT)            // 408
#define ICSTR 2456                // 6*408=2448 + 8 pad: (24q+r)%32 all-distinct
#define SMEM_K3 ((8*ICSTR + 4 + 1728 + 32) * 4)

__global__ void __launch_bounds__(256, 2) k_conv(const float* __restrict__ x,
                                                 const float* __restrict__ w3) {
    extern __shared__ float smraw[];
    float* s_in  = smraw + 3;              // skew: halo col1 16B-aligned
    float* s_wt  = smraw + 8*ICSTR + 4;    // tf32-rounded weights [oc*216 + ic*27 + tap]
    float* s_red = s_wt + 1728;            // [0..7]=bnsum [8..15]=bnsq [16..23]=tsum [24..31]=tsq

    int zc = blockIdx.x;   // 0..15
    int yc = blockIdx.y;   // 0..15
    int n  = blockIdx.z;   // 0..15
    int t  = threadIdx.x;
    int lane = t & 31, wid = t >> 5;
    int zq = wid & 3;            // z within chunk
    int yh = wid >> 2;           // 0..1 (2 y rows each)
    int q  = lane & 3;           // k-group selector (ic=q and ic=q+4)
    int r  = lane >> 2;          // row group 0..7 (w and oc)

    for (int i = t; i < 1728; i += 256)
        s_wt[i] = __uint_as_float(f2tf32(w3[i]));
    if (t < 32) s_red[t] = 0.f;
    // zero the always-zero w-halo columns once: 8 ic x 6 z x 6 y rows = 288
    for (int i = t; i < 288; i += 256) {
        int icl = i / 36, rem = i % 36;
        int zz = rem / 6, yy = rem % 6;
        float* rp = s_in + icl*ICSTR + zz*ZSTR + yy*SWT;
        rp[0] = 0.f; rp[65] = 0.f; rp[66] = 0.f; rp[67] = 0.f;
    }

    const float* xb = x + (size_t)n * CGc * SPL;
    int z0 = zc * 4 - 1, y0 = yc * 4 - 1;
    int gz = zc * 4 + zq;

    // fill mapping: fl = w quad (16 lanes), fp = y halo row (active < 6)
    int fl = t & 15;
    int fp = t >> 4;
    int gyf = y0 + fp;
    bool fpact = (fp < 6);
    bool gyok  = fpact && ((unsigned)gyf < 64u);

    float acc[8][4];   // [wq*2+yy][c0..c3]
#pragma unroll
    for (int i = 0; i < 8; i++) {
        acc[i][0] = 0.f; acc[i][1] = 0.f; acc[i][2] = 0.f; acc[i][3] = 0.f;
    }

    // structured vectorized fill: 8 ic x 6 z rows of 64 w (float4)
    {
        const float* srcb = xb + (size_t)gyf * 64 + fl*4;
        float* dstb = s_in + fp*SWT + 1 + fl*4;
#pragma unroll
        for (int icl = 0; icl < 8; icl++) {
#pragma unroll
            for (int zz = 0; zz < 6; zz++) {
                int gzf = z0 + zz;
                float4 v = make_float4(0.f, 0.f, 0.f, 0.f);
                if (gyok && (unsigned)gzf < 64u)
                    v = *(const float4*)(srcb + (size_t)icl*SPL + (size_t)gzf*PLANE);
                if (fpact) {
                    float4 o;
                    o.x = __uint_as_float(f2tf32(v.x));
                    o.y = __uint_as_float(f2tf32(v.y));
                    o.z = __uint_as_float(f2tf32(v.z));
                    o.w = __uint_as_float(f2tf32(v.w));
                    *(float4*)(dstb + icl*ICSTR + zz*ZSTR) = o;
                }
            }
        }
    }
    __syncthreads();

    // MMA mainloop: kd outer, taps(kh,kw) x 8 tiles unrolled inside. K=8 (all ic).
    {
        const float* apk  = s_in + q*ICSTR + zq*ZSTR + yh*(2*SWT) + r;          // ic = q
        const float* apk2 = apk + 4*ICSTR;                                      // ic = q+4
        const float* wb0 = s_wt + r*216 + q*27;          // b0: oc=r, ic=q
        const float* wb1 = s_wt + r*216 + (q+4)*27;      // b1: oc=r, ic=q+4
#pragma unroll 1
        for (int kd = 0; kd < 3; kd++) {
            unsigned bf0[9], bf1[9];
#pragma unroll
            for (int j = 0; j < 9; j++) {
                bf0[j] = __float_as_uint(wb0[kd*9 + j]);
                bf1[j] = __float_as_uint(wb1[kd*9 + j]);
            }
#pragma unroll
            for (int kh = 0; kh < 3; kh++) {
#pragma unroll
                for (int kw = 0; kw < 3; kw++) {
                    const int koff = kh*SWT + kw;
#pragma unroll
                    for (int i = 0; i < 8; i++) {
                        const int toff = (i >> 1)*16 + (i & 1)*SWT + koff;
                        unsigned a0 = __float_as_uint(apk[toff]);
                        unsigned a1 = __float_as_uint(apk[toff + 8]);
                        unsigned a2 = __float_as_uint(apk2[toff]);
                        unsigned a3 = __float_as_uint(apk2[toff + 8]);
                        asm volatile(
                            "mma.sync.aligned.m16n8k8.row.col.f32.tf32.tf32.f32 "
                            "{%0,%1,%2,%3}, {%4,%5,%6,%7}, {%8,%9}, {%0,%1,%2,%3};"
                            : "+f"(acc[i][0]), "+f"(acc[i][1]),
                              "+f"(acc[i][2]), "+f"(acc[i][3])
                            : "r"(a0), "r"(a1), "r"(a2), "r"(a3),
                              "r"(bf0[kh*3 + kw]), "r"(bf1[kh*3 + kw]));
                    }
                }
            }
            apk += ZSTR; apk2 += ZSTR;
        }
    }

    // GN stats of t = x * a_h*a_w*a_d for all 8 channels
    {
        int w_ = t & 63, zq4 = t >> 6;
        for (int c = 0; c < 8; c++) {
            const float* ab = g_a + (n*8 + c) * 192;
            float ahz = __ldg(ab + zc*4 + zq4);
            float adw = __ldg(ab + 128 + w_);
            float tp = 0.f, tq = 0.f;
#pragma unroll
            for (int yy = 0; yy < 4; yy++) {
                float aw = __ldg(ab + 64 + yc*4 + yy);
                float v  = s_in[c*ICSTR + (zq4 + 1)*ZSTR + (yy + 1)*SWT + (w_ + 1)];
                float tv = v * ahz * aw * adw;
                tp += tv; tq += tv * tv;
            }
#pragma unroll
            for (int o = 16; o > 0; o >>= 1) {
                tp += __shfl_down_sync(0xffffffffu, tp, o);
                tq += __shfl_down_sync(0xffffffffu, tq, o);
            }
            if ((t & 31) == 0) { atomicAdd(&s_red[16 + c], tp); atomicAdd(&s_red[24 + c], tq); }
        }
    }

    // epilogue: store raw conv + per-oc partial stats
    int oc0 = 2*q, oc1 = oc0 + 1;
    float* ob0 = g_x2raw + (size_t)(n*8 + oc0) * SPL + gz * PLANE;
    float* ob1 = g_x2raw + (size_t)(n*8 + oc1) * SPL + gz * PLANE;
    float ls0 = 0.f, lq0 = 0.f, ls1 = 0.f, lq1 = 0.f;
#pragma unroll
    for (int wq = 0; wq < 4; wq++) {
#pragma unroll
        for (int yy = 0; yy < 2; yy++) {
            int gy = yc*4 + yh*2 + yy;
            int wb = wq*16 + r;
            float c0 = acc[wq*2+yy][0], c1 = acc[wq*2+yy][1];
            float c2 = acc[wq*2+yy][2], c3 = acc[wq*2+yy][3];
            ob0[gy*64 + wb]     = c0;
            ob1[gy*64 + wb]     = c1;
            ob0[gy*64 + wb + 8] = c2;
            ob1[gy*64 + wb + 8] = c3;
            ls0 += c0 + c2; lq0 += c0*c0 + c2*c2;
            ls1 += c1 + c3; lq1 += c1*c1 + c3*c3;
        }
    }
#pragma unroll
    for (int o = 4; o < 32; o <<= 1) {
        ls0 += __shfl_xor_sync(0xffffffffu, ls0, o);
        lq0 += __shfl_xor_sync(0xffffffffu, lq0, o);
        ls1 += __shfl_xor_sync(0xffffffffu, ls1, o);
        lq1 += __shfl_xor_sync(0xffffffffu, lq1, o);
    }
    if (r == 0) {
        atomicAdd(&s_red[oc0], ls0); atomicAdd(&s_red[8 + oc0], lq0);
        atomicAdd(&s_red[oc1], ls1); atomicAdd(&s_red[8 + oc1], lq1);
    }
    __syncthreads();
    if (t < 8) {
        atomicAdd(&g_bnsum[t], s_red[t]);
        atomicAdd(&g_bnsq[t],  s_red[8 + t]);
        atomicAdd(&g_tsum[n*8 + t], s_red[16 + t]);
        atomicAdd(&g_tsq[n*8 + t],  s_red[24 + t]);
    }
}

// ---------------- K4: finalize GN / BN3 affine params ----------------
__global__ void k_stats(const float* __restrict__ gng, const float* __restrict__ gnb,
                        const float* __restrict__ bn3g, const float* __restrict__ bn3b) {
    int t = threadIdx.x;   // 128
    if (t < 128) {
        float m   = g_tsum[t] * (1.f / (float)SPL);
        float var = g_tsq[t]  * (1.f / (float)SPL) - m * m;
        float rs  = rsqrtf(var + 1e-5f);
        int c = t & 7;
        float sc = gng[c] * rs;
        g_gnscale[t] = sc;
        g_gnshift[t] = gnb[c] - m * sc;
    }
    if (t < 8) {
        const float inv = 1.f / (16.f * (float)SPL);
        float m   = g_bnsum[t] * inv;
        float var = g_bnsq[t]  * inv - m * m;
        float rs  = rsqrtf(var + 1e-5f);
        float sc  = bn3g[t] * rs;
        g_bnscale[t] = sc;
        g_bnshift[t] = bn3b[t] - m * sc;     // conv bias cancels inside BN
    }
}

// ---------------- K5: per-(n,c) mean of relu(BN3(conv)) ----------------
__global__ void __launch_bounds__(256) k_x2mean() {
    int nc = blockIdx.x >> 3, ch = blockIdx.x & 7;
    int t = threadIdx.x;
    float bs  = g_bnscale[nc & 7];
    float bsh = g_bnshift[nc & 7];
    const float4* rp = (const float4*)(g_x2raw + (size_t)nc * SPL) + ch * 8192;
    float s = 0.f;
    for (int i = t; i < 8192; i += 256) {
        float4 v = rp[i];
        s += fmaxf(fmaf(bs, v.x, bsh), 0.f) + fmaxf(fmaf(bs, v.y, bsh), 0.f)
           + fmaxf(fmaf(bs, v.z, bsh), 0.f) + fmaxf(fmaf(bs, v.w, bsh), 0.f);
    }
#pragma unroll
    for (int o = 16; o > 0; o >>= 1) s += __shfl_down_sync(0xffffffffu, s, o);
    __shared__ float sw[8];
    if ((t & 31) == 0) sw[t >> 5] = s;
    __syncthreads();
    if (t == 0) {
        float tot = 0.f;
        for (int i = 0; i < 8; i++) tot += sw[i];
        atomicAdd(&g_x2sum[nc], tot);
    }
}

// ---------------- K6: softmaxes ----------------
__global__ void k_soft(const float* __restrict__ gnb) {
    int t = threadIdx.x;   // 32
    if (t < 16) {
        float v[8], mx = -1e30f;
        for (int c = 0; c < 8; c++) { v[c] = g_x2sum[t*8 + c] * (1.f / (float)SPL); mx = fmaxf(mx, v[c]); }
        float sum = 0.f;
        for (int c = 0; c < 8; c++) { v[c] = expf(v[c] - mx); sum += v[c]; }
        for (int c = 0; c < 8; c++) g_x21[t*8 + c] = v[c] / sum;
    }
    if (t == 16) {
        float v[8], mx = -1e30f;
        for (int c = 0; c < 8; c++) { v[c] = gnb[c]; mx = fmaxf(mx, v[c]); }   // mean(x1) == gn_b exactly
        float sum = 0.f;
        for (int c = 0; c < 8; c++) { v[c] = expf(v[c] - mx); sum += v[c]; }
        for (int c = 0; c < 8; c++) g_x11[c] = v[c] / sum;
    }
}

// ---------------- K7: fused weights + sigmoid gate + output ----------------
__global__ void __launch_bounds__(256) k_out(const float* __restrict__ x,
                                             float* __restrict__ out) {
    int n  = blockIdx.x >> 6;
    int pc = blockIdx.x & 63;
    int t  = threadIdx.x;

    __shared__ float s_x11[8], s_x21[8], s_gs[8], s_gsh[8], s_bs[8], s_bsh[8];
    if (t < 8) {
        s_x11[t] = g_x11[t];
        s_x21[t] = g_x21[n*8 + t];
        s_gs[t]  = g_gnscale[n*8 + t];
        s_gsh[t] = g_gnshift[n*8 + t];
        s_bs[t]  = g_bnscale[t];
        s_bsh[t] = g_bnshift[t];
    }
    __syncthreads();

    const float4* xp = (const float4*)(x + (size_t)n * 8 * SPL);
    const float4* rp = (const float4*)(g_x2raw + (size_t)n * 8 * SPL);
    float4* op = (float4*)(out + (size_t)n * 8 * SPL);

    for (int it = 0; it < 4; it++) {
        int p4 = pc * 1024 + it * 256 + t;    // float4 index within SPL/4
        int p  = p4 * 4;
        int z = p >> 12, y = (p >> 6) & 63, w0 = p & 63;

        float4 xs[8];
        float4 ws; ws.x = 0.f; ws.y = 0.f; ws.z = 0.f; ws.w = 0.f;
#pragma unroll
        for (int c = 0; c < 8; c++) {
            float4 xv = xp[c * (SPL/4) + p4];
            float4 rv = rp[c * (SPL/4) + p4];
            xs[c] = xv;
            const float* ab = g_a + (n*8 + c) * 192;
            float ah = __ldg(ab + z);
            float aw = __ldg(ab + 64 + y);
            float4 ad = *(const float4*)(ab + 128 + w0);
            float haw = ah * aw;
            float gs = s_gs[c], gsh = s_gsh[c];
            float bs = s_bs[c], bsh = s_bsh[c];
            float x11c = s_x11[c], x21c = s_x21[c];
            ws.x += x11c * fmaxf(fmaf(bs, rv.x, bsh), 0.f) + x21c * fmaf(gs, xv.x * haw * ad.x, gsh);
            ws.y += x11c * fmaxf(fmaf(bs, rv.y, bsh), 0.f) + x21c * fmaf(gs, xv.y * haw * ad.y, gsh);
            ws.z += x11c * fmaxf(fmaf(bs, rv.z, bsh), 0.f) + x21c * fmaf(gs, xv.z * haw * ad.z, gsh);
            ws.w += x11c * fmaxf(fmaf(bs, rv.w, bsh), 0.f) + x21c * fmaf(gs, xv.w * haw * ad.w, gsh);
        }
        float4 sg;
        sg.x = 1.f / (1.f + expf(-ws.x));
        sg.y = 1.f / (1.f + expf(-ws.y));
        sg.z = 1.f / (1.f + expf(-ws.z));
        sg.w = 1.f / (1.f + expf(-ws.w));
#pragma unroll
        for (int c = 0; c < 8; c++) {
            float4 o4;
            o4.x = xs[c].x * sg.x;
            o4.y = xs[c].y * sg.y;
            o4.z = xs[c].z * sg.z;
            o4.w = xs[c].w * sg.w;
            op[c * (SPL/4) + p4] = o4;
        }
    }
}

// ---------------- launch ----------------
extern "C" void kernel_launch(void* const* d_in, const int* in_sizes, int n_in,
                              void* d_out, int out_size) {
    const float* x    = (const float*)d_in[0];
    const float* c1w  = (const float*)d_in[1];
    const float* c1b  = (const float*)d_in[2];
    const float* bn1g = (const float*)d_in[3];
    const float* bn1b = (const float*)d_in[4];
    const float* c3w  = (const float*)d_in[5];
    // d_in[6] = conv3_b : cancels inside BN3, unused
    const float* bn3g = (const float*)d_in[7];
    const float* bn3b = (const float*)d_in[8];
    const float* gng  = (const float*)d_in[9];
    const float* gnb  = (const float*)d_in[10];
    float* out = (float*)d_out;

    cudaFuncSetAttribute(k_conv, cudaFuncAttributeMaxDynamicSharedMemorySize, SMEM_K3);

    k_zero<<<96, 256>>>();
    k_pool<<<dim3(128, 4), 256>>>(x);
    k_excite<<<1, 1024>>>(c1w, c1b, bn1g, bn1b);
    k_conv<<<dim3(16, 16, 16), 256, SMEM_K3>>>(x, c3w);
    k_stats<<<1, 128>>>(gng, gnb, bn3g, bn3b);
    k_x2mean<<<1024, 256>>>();
    k_soft<<<1, 32>>>(gnb);
    k_out<<<1024, 256>>>(x, out);
}

// round 17
// speedup vs baseline: 1.7634x; 1.7634x over previous
#include <cuda_runtime.h>
#include <math.h>

#define NBG 16          // b*g
#define CGc 8           // channels per group
#define SPL 262144      // 64*64*64
#define PLANE 4096      // 64*64

// ---------------- device scratch (static, no runtime alloc) ----------------
__device__ float g_pool[NBG*CGc*192];
__device__ float g_a[NBG*CGc*192];
__device__ float g_x2raw[(size_t)NBG*CGc*SPL];   // 134 MB raw conv output
__device__ float g_tsum[NBG*CGc];
__device__ float g_tsq[NBG*CGc];
__device__ float g_bnsum[CGc];
__device__ float g_bnsq[CGc];
__device__ float g_gnscale[NBG*CGc];
__device__ float g_gnshift[NBG*CGc];
__device__ float g_bnscale[CGc];
__device__ float g_bnshift[CGc];
__device__ float g_x2sum[NBG*CGc];
__device__ float g_x11[CGc];
__device__ float g_x21[NBG*CGc];

__device__ __forceinline__ unsigned f2tf32(float v) {
    unsigned u;
    asm("cvt.rna.tf32.f32 %0, %1;" : "=r"(u) : "f"(v));
    return u;
}
__device__ __forceinline__ void cp_async16(unsigned smem_addr, const void* gptr, int src_size) {
    asm volatile("cp.async.cg.shared.global [%0], [%1], 16, %2;"
                 :: "r"(smem_addr), "l"(gptr), "r"(src_size));
}

// ---------------- K0: zero accumulators ----------------
__global__ void k_zero() {
    int i = blockIdx.x * 256 + threadIdx.x;
    if (i < NBG*CGc*192) g_pool[i] = 0.f;
    if (i < NBG*CGc) { g_tsum[i] = 0.f; g_tsq[i] = 0.f; g_x2sum[i] = 0.f; }
    if (i < CGc) { g_bnsum[i] = 0.f; g_bnsq[i] = 0.f; }
}

// ---------------- K1: directional pools ----------------
__global__ void __launch_bounds__(256) k_pool(const float* __restrict__ x) {
    int nc = blockIdx.x;
    int q  = blockIdx.y;                 // d chunk 0..3
    const float* base = x + (size_t)nc * SPL;
    int t  = threadIdx.x;
    int w_ = t & 63, hb = t >> 6;        // hb 0..3

    __shared__ float s_h[16], s_w[64], s_d[64];
    if (t < 16) s_h[t] = 0.f;
    if (t < 64) { s_w[t] = 0.f; s_d[t] = 0.f; }
    __syncthreads();

    float hpart[16];
#pragma unroll
    for (int k = 0; k < 16; k++) hpart[k] = 0.f;
    float sdp = 0.f;

    for (int dd = 0; dd < 16; dd++) {
        int d = q * 16 + dd;
        const float* pl = base + d * PLANE;
        float ps = 0.f;
#pragma unroll
        for (int k = 0; k < 16; k++) {
            float v = pl[(hb + 4*k) * 64 + w_];
            ps += v;
            hpart[k] += v;
        }
        sdp += ps;
#pragma unroll
        for (int o = 16; o > 0; o >>= 1) ps += __shfl_down_sync(0xffffffffu, ps, o);
        if ((t & 31) == 0) atomicAdd(&s_h[dd], ps);
    }
#pragma unroll
    for (int k = 0; k < 16; k++) {
        float v = hpart[k];
#pragma unroll
        for (int o = 16; o > 0; o >>= 1) v += __shfl_down_sync(0xffffffffu, v, o);
        if ((t & 31) == 0) atomicAdd(&s_w[hb + 4*k], v);
    }
    atomicAdd(&s_d[w_], sdp);
    __syncthreads();

    float* outp = g_pool + nc * 192;
    if (t < 16) outp[q * 16 + t] = s_h[t];            // exclusive per (nc,q)
    if (t < 64) {
        atomicAdd(&outp[64  + t], s_w[t]);
        atomicAdd(&outp[128 + t], s_d[t]);
    }
}

// ---------------- K2: conv1(1x1x1) + BN1(train) + ReLU + sigmoid ----------------
__global__ void __launch_bounds__(1024) k_excite(const float* __restrict__ w1,
                                                 const float* __restrict__ b1,
                                                 const float* __restrict__ bn1g,
                                                 const float* __restrict__ bn1b) {
    __shared__ float s_w1[64], s_sum[8], s_sq[8], s_scale[8], s_shift[8];
    int t = threadIdx.x;
    if (t < 64) s_w1[t] = w1[t];
    if (t < 8) { s_sum[t] = 0.f; s_sq[t] = 0.f; }
    __syncthreads();

    int o = t >> 7;       // output channel 0..7
    int j = t & 127;      // position within o-group
    float bo = b1[o];
    float lsum = 0.f, lsq = 0.f;

    for (int i = 0; i < 24; i++) {
        int idx = j + (i << 7);           // 0..3071  -> (n,s)
        int n = idx / 192, s = idx - n * 192;
        float dot = 0.f;
#pragma unroll
        for (int ic = 0; ic < 8; ic++)
            dot += s_w1[o*8 + ic] * g_pool[(n*8 + ic)*192 + s];
        float h = bo + dot * (1.f / 4096.f);
        g_a[(n*8 + o)*192 + s] = h;       // stage hwd
        lsum += h; lsq += h * h;
    }
#pragma unroll
    for (int oo = 16; oo > 0; oo >>= 1) {
        lsum += __shfl_down_sync(0xffffffffu, lsum, oo);
        lsq  += __shfl_down_sync(0xffffffffu, lsq,  oo);
    }
    if ((t & 31) == 0) { atomicAdd(&s_sum[o], lsum); atomicAdd(&s_sq[o], lsq); }
    __syncthreads();
    if (t < 8) {
        float m   = s_sum[t] * (1.f / 3072.f);
        float var = s_sq[t]  * (1.f / 3072.f) - m * m;
        float rs  = rsqrtf(var + 1e-5f);
        float sc  = bn1g[t] * rs;
        s_scale[t] = sc;
        s_shift[t] = bn1b[t] - m * sc;
    }
    __syncthreads();
    float sc = s_scale[o], sh = s_shift[o];
    for (int i = 0; i < 24; i++) {
        int idx = j + (i << 7);
        int n = idx / 192, s = idx - n * 192;
        int e = (n*8 + o)*192 + s;
        float h = g_a[e];
        float y = fmaxf(fmaf(sc, h, sh), 0.f);
        g_a[e] = 1.f / (1.f + expf(-y));
    }
}

// ---------------- K3: 3x3x3 conv via tf32 m16n8k4 mma.sync + BN3/GN stats ----------------
// R12 shell: CTA tile z=4, y=8, w=64; 2 passes of 4 ic; tap-outer/tile-inner MMA order.
// Fill via cp.async (no register round-trip, no input cvt: HW truncates fp32->tf32).
#define SZT 6
#define SYT 10
#define SWT 68
#define ZSTR (SYT*SWT)            // 680
#define ICSTR 4088                // padded: conflict-free LDS across q lanes
#define SMEM_K3 ((4*ICSTR + 4 + 1728 + 32) * 4)

__global__ void __launch_bounds__(256, 2) k_conv(const float* __restrict__ x,
                                                 const float* __restrict__ w3) {
    extern __shared__ float smraw[];
    float* s_in  = smraw + 3;              // skew: row base ≡ 3 mod 4 -> col1 16B-aligned
    float* s_wt  = smraw + 4*ICSTR + 4;    // tf32-rounded weights [oc*216 + ic*27 + tap]
    float* s_red = s_wt + 1728;            // [0..7]=bnsum [8..15]=bnsq [16..23]=tsum [24..31]=tsq

    int zc = blockIdx.x;   // 0..15
    int yc = blockIdx.y;   // 0..7
    int n  = blockIdx.z;   // 0..15
    int t  = threadIdx.x;
    int lane = t & 31, wid = t >> 5;
    int zq = wid & 3;            // z within chunk
    int yh = wid >> 2;           // 0..1 (4 y rows each)
    int q  = lane & 3;           // k-col / oc-pair selector
    int r  = lane >> 2;          // row group 0..7

    for (int i = t; i < 1728; i += 256)
        s_wt[i] = __uint_as_float(f2tf32(w3[i]));
    if (t < 32) s_red[t] = 0.f;
    // zero the always-zero w-halo columns once (cols 0,65,66,67 of each row)
    if (t < 240) {
        int icl = t / 60, rem = t % 60;
        int zz = rem / 10, yy = rem % 10;
        float* rp = s_in + icl*ICSTR + zz*ZSTR + yy*SWT;
        rp[0] = 0.f; rp[65] = 0.f; rp[66] = 0.f; rp[67] = 0.f;
    }

    const float* xb = x + (size_t)n * CGc * SPL;
    int z0 = zc * 4 - 1, y0 = yc * 8 - 1;
    int gz = zc * 4 + zq;

    // fill mapping: fl = w quad (16 lanes), fp = yy row (active < 10)
    int fl = t & 15;
    int fp = t >> 4;
    int gyf = y0 + fp;
    bool fpact = (fp < 10);
    bool gyok  = fpact && ((unsigned)gyf < 64u);
    int gyc = gyf < 0 ? 0 : (gyf > 63 ? 63 : gyf);   // clamped (src ignored when size=0)

    float acc[16][4];   // [wq*4+yy][c0..c3]
#pragma unroll
    for (int i = 0; i < 16; i++) {
        acc[i][0] = 0.f; acc[i][1] = 0.f; acc[i][2] = 0.f; acc[i][3] = 0.f;
    }

    unsigned s_in_u32 = (unsigned)__cvta_generic_to_shared(s_in);

#pragma unroll 1
    for (int pass = 0; pass < 2; pass++) {
        if (pass) __syncthreads();      // protect previous pass's s_in readers
        // cp.async fill: 4 ic x 6 z rows of 64 w, 16B lines, zero-fill when OOB
        if (fpact) {
            const char* srcb = (const char*)(xb + (size_t)(pass*4) * SPL + (size_t)gyc * 64 + fl*4);
            unsigned dstb = s_in_u32 + (fp*SWT + 1 + fl*4) * 4;
#pragma unroll
            for (int icl = 0; icl < 4; icl++) {
#pragma unroll
                for (int zz = 0; zz < 6; zz++) {
                    int gzf = z0 + zz;
                    int gzc = gzf < 0 ? 0 : (gzf > 63 ? 63 : gzf);
                    int ssz = (gyok && (unsigned)gzf < 64u) ? 16 : 0;
                    cp_async16(dstb + (icl*ICSTR + zz*ZSTR) * 4,
                               srcb + ((size_t)icl*SPL + (size_t)gzc*PLANE) * 4, ssz);
                }
            }
        }
        asm volatile("cp.async.commit_group;");
        asm volatile("cp.async.wait_group 0;");
        __syncthreads();

        // MMA mainloop: kd as outer loop, taps(kh,kw) x 16 tiles fully unrolled inside.
        {
            const float* apk = s_in + q*ICSTR + zq*ZSTR + yh*(4*SWT) + r;
            const float* wbase = s_wt + r*216 + (pass*4 + q)*27;
#pragma unroll 1
            for (int kd = 0; kd < 3; kd++) {
                // 9 B-fragments for this kd
                unsigned bfk[9];
#pragma unroll
                for (int j = 0; j < 9; j++) bfk[j] = __float_as_uint(wbase[kd*9 + j]);
#pragma unroll
                for (int kh = 0; kh < 3; kh++) {
#pragma unroll
                    for (int kw = 0; kw < 3; kw++) {
                        const int koff = kh*SWT + kw;
#pragma unroll
                        for (int i = 0; i < 16; i++) {
                            const int toff = (i >> 2)*16 + (i & 3)*SWT + koff;
                            unsigned a0 = __float_as_uint(apk[toff]);
                            unsigned a1 = __float_as_uint(apk[toff + 8]);
                            asm volatile(
                                "mma.sync.aligned.m16n8k4.row.col.f32.tf32.tf32.f32 "
                                "{%0,%1,%2,%3}, {%4,%5}, {%6}, {%0,%1,%2,%3};"
                                : "+f"(acc[i][0]), "+f"(acc[i][1]),
                                  "+f"(acc[i][2]), "+f"(acc[i][3])
                                : "r"(a0), "r"(a1), "r"(bfk[kh*3 + kw]));
                        }
                    }
                }
                apk += ZSTR;
            }
        }

        // GN stats of t = x * a_h*a_w*a_d for this pass's 4 channels (exact x now)
        {
            int w_ = t & 63, zq4 = t >> 6;
            for (int cl = 0; cl < 4; cl++) {
                int c = pass * 4 + cl;
                const float* ab = g_a + (n*8 + c) * 192;
                float ahz = __ldg(ab + zc*4 + zq4);
                float adw = __ldg(ab + 128 + w_);
                float tp = 0.f, tq = 0.f;
#pragma unroll
                for (int yy = 0; yy < 8; yy++) {
                    float aw = __ldg(ab + 64 + yc*8 + yy);
                    float v  = s_in[cl*ICSTR + (zq4 + 1)*ZSTR + (yy + 1)*SWT + (w_ + 1)];
                    float tv = v * ahz * aw * adw;
                    tp += tv; tq += tv * tv;
                }
#pragma unroll
                for (int o = 16; o > 0; o >>= 1) {
                    tp += __shfl_down_sync(0xffffffffu, tp, o);
                    tq += __shfl_down_sync(0xffffffffu, tq, o);
                }
                if ((t & 31) == 0) { atomicAdd(&s_red[16 + c], tp); atomicAdd(&s_red[24 + c], tq); }
            }
        }
    }

    // epilogue: store raw conv + per-oc partial stats
    int oc0 = 2*q, oc1 = oc0 + 1;
    float* ob0 = g_x2raw + (size_t)(n*8 + oc0) * SPL + gz * PLANE;
    float* ob1 = g_x2raw + (size_t)(n*8 + oc1) * SPL + gz * PLANE;
    float ls0 = 0.f, lq0 = 0.f, ls1 = 0.f, lq1 = 0.f;
#pragma unroll
    for (int wq = 0; wq < 4; wq++) {
#pragma unroll
        for (int yy = 0; yy < 4; yy++) {
            int gy = yc*8 + yh*4 + yy;
            int wb = wq*16 + r;
            float c0 = acc[wq*4+yy][0], c1 = acc[wq*4+yy][1];
            float c2 = acc[wq*4+yy][2], c3 = acc[wq*4+yy][3];
            ob0[gy*64 + wb]     = c0;
            ob1[gy*64 + wb]     = c1;
            ob0[gy*64 + wb + 8] = c2;
            ob1[gy*64 + wb + 8] = c3;
            ls0 += c0 + c2; lq0 += c0*c0 + c2*c2;
            ls1 += c1 + c3; lq1 += c1*c1 + c3*c3;
        }
    }
#pragma unroll
    for (int o = 4; o < 32; o <<= 1) {
        ls0 += __shfl_xor_sync(0xffffffffu, ls0, o);
        lq0 += __shfl_xor_sync(0xffffffffu, lq0, o);
        ls1 += __shfl_xor_sync(0xffffffffu, ls1, o);
        lq1 += __shfl_xor_sync(0xffffffffu, lq1, o);
    }
    if (r == 0) {
        atomicAdd(&s_red[oc0], ls0); atomicAdd(&s_red[8 + oc0], lq0);
        atomicAdd(&s_red[oc1], ls1); atomicAdd(&s_red[8 + oc1], lq1);
    }
    __syncthreads();
    if (t < 8) {
        atomicAdd(&g_bnsum[t], s_red[t]);
        atomicAdd(&g_bnsq[t],  s_red[8 + t]);
        atomicAdd(&g_tsum[n*8 + t], s_red[16 + t]);
        atomicAdd(&g_tsq[n*8 + t],  s_red[24 + t]);
    }
}

// ---------------- K4: finalize GN / BN3 affine params ----------------
__global__ void k_stats(const float* __restrict__ gng, const float* __restrict__ gnb,
                        const float* __restrict__ bn3g, const float* __restrict__ bn3b) {
    int t = threadIdx.x;   // 128
    if (t < 128) {
        float m   = g_tsum[t] * (1.f / (float)SPL);
        float var = g_tsq[t]  * (1.f / (float)SPL) - m * m;
        float rs  = rsqrtf(var + 1e-5f);
        int c = t & 7;
        float sc = gng[c] * rs;
        g_gnscale[t] = sc;
        g_gnshift[t] = gnb[c] - m * sc;
    }
    if (t < 8) {
        const float inv = 1.f / (16.f * (float)SPL);
        float m   = g_bnsum[t] * inv;
        float var = g_bnsq[t]  * inv - m * m;
        float rs  = rsqrtf(var + 1e-5f);
        float sc  = bn3g[t] * rs;
        g_bnscale[t] = sc;
        g_bnshift[t] = bn3b[t] - m * sc;     // conv bias cancels inside BN
    }
}

// ---------------- K5: per-(n,c) mean of relu(BN3(conv)) ----------------
__global__ void __launch_bounds__(256) k_x2mean() {
    int nc = blockIdx.x >> 3, ch = blockIdx.x & 7;
    int t = threadIdx.x;
    float bs  = g_bnscale[nc & 7];
    float bsh = g_bnshift[nc & 7];
    const float4* rp = (const float4*)(g_x2raw + (size_t)nc * SPL) + ch * 8192;
    float s = 0.f;
    for (int i = t; i < 8192; i += 256) {
        float4 v = rp[i];
        s += fmaxf(fmaf(bs, v.x, bsh), 0.f) + fmaxf(fmaf(bs, v.y, bsh), 0.f)
           + fmaxf(fmaf(bs, v.z, bsh), 0.f) + fmaxf(fmaf(bs, v.w, bsh), 0.f);
    }
#pragma unroll
    for (int o = 16; o > 0; o >>= 1) s += __shfl_down_sync(0xffffffffu, s, o);
    __shared__ float sw[8];
    if ((t & 31) == 0) sw[t >> 5] = s;
    __syncthreads();
    if (t == 0) {
        float tot = 0.f;
        for (int i = 0; i < 8; i++) tot += sw[i];
        atomicAdd(&g_x2sum[nc], tot);
    }
}

// ---------------- K6: softmaxes ----------------
__global__ void k_soft(const float* __restrict__ gnb) {
    int t = threadIdx.x;   // 32
    if (t < 16) {
        float v[8], mx = -1e30f;
        for (int c = 0; c < 8; c++) { v[c] = g_x2sum[t*8 + c] * (1.f / (float)SPL); mx = fmaxf(mx, v[c]); }
        float sum = 0.f;
        for (int c = 0; c < 8; c++) { v[c] = expf(v[c] - mx); sum += v[c]; }
        for (int c = 0; c < 8; c++) g_x21[t*8 + c] = v[c] / sum;
    }
    if (t == 16) {
        float v[8], mx = -1e30f;
        for (int c = 0; c < 8; c++) { v[c] = gnb[c]; mx = fmaxf(mx, v[c]); }   // mean(x1) == gn_b exactly
        float sum = 0.f;
        for (int c = 0; c < 8; c++) { v[c] = expf(v[c] - mx); sum += v[c]; }
        for (int c = 0; c < 8; c++) g_x11[c] = v[c] / sum;
    }
}

// ---------------- K7: fused weights + sigmoid gate + output ----------------
__global__ void __launch_bounds__(256) k_out(const float* __restrict__ x,
                                             float* __restrict__ out) {
    int n  = blockIdx.x >> 6;
    int pc = blockIdx.x & 63;
    int t  = threadIdx.x;

    __shared__ float s_x11[8], s_x21[8], s_gs[8], s_gsh[8], s_bs[8], s_bsh[8];
    if (t < 8) {
        s_x11[t] = g_x11[t];
        s_x21[t] = g_x21[n*8 + t];
        s_gs[t]  = g_gnscale[n*8 + t];
        s_gsh[t] = g_gnshift[n*8 + t];
        s_bs[t]  = g_bnscale[t];
        s_bsh[t] = g_bnshift[t];
    }
    __syncthreads();

    const float4* xp = (const float4*)(x + (size_t)n * 8 * SPL);
    const float4* rp = (const float4*)(g_x2raw + (size_t)n * 8 * SPL);
    float4* op = (float4*)(out + (size_t)n * 8 * SPL);

    for (int it = 0; it < 4; it++) {
        int p4 = pc * 1024 + it * 256 + t;    // float4 index within SPL/4
        int p  = p4 * 4;
        int z = p >> 12, y = (p >> 6) & 63, w0 = p & 63;

        float4 xs[8];
        float4 ws; ws.x = 0.f; ws.y = 0.f; ws.z = 0.f; ws.w = 0.f;
#pragma unroll
        for (int c = 0; c < 8; c++) {
            float4 xv = xp[c * (SPL/4) + p4];
            float4 rv = rp[c * (SPL/4) + p4];
            xs[c] = xv;
            const float* ab = g_a + (n*8 + c) * 192;
            float ah = __ldg(ab + z);
            float aw = __ldg(ab + 64 + y);
            float4 ad = *(const float4*)(ab + 128 + w0);
            float haw = ah * aw;
            float gs = s_gs[c], gsh = s_gsh[c];
            float bs = s_bs[c], bsh = s_bsh[c];
            float x11c = s_x11[c], x21c = s_x21[c];
            ws.x += x11c * fmaxf(fmaf(bs, rv.x, bsh), 0.f) + x21c * fmaf(gs, xv.x * haw * ad.x, gsh);
            ws.y += x11c * fmaxf(fmaf(bs, rv.y, bsh), 0.f) + x21c * fmaf(gs, xv.y * haw * ad.y, gsh);
            ws.z += x11c * fmaxf(fmaf(bs, rv.z, bsh), 0.f) + x21c * fmaf(gs, xv.z * haw * ad.z, gsh);
            ws.w += x11c * fmaxf(fmaf(bs, rv.w, bsh), 0.f) + x21c * fmaf(gs, xv.w * haw * ad.w, gsh);
        }
        float4 sg;
        sg.x = 1.f / (1.f + expf(-ws.x));
        sg.y = 1.f / (1.f + expf(-ws.y));
        sg.z = 1.f / (1.f + expf(-ws.z));
        sg.w = 1.f / (1.f + expf(-ws.w));
#pragma unroll
        for (int c = 0; c < 8; c++) {
            float4 o4;
            o4.x = xs[c].x * sg.x;
            o4.y = xs[c].y * sg.y;
            o4.z = xs[c].z * sg.z;
            o4.w = xs[c].w * sg.w;
            op[c * (SPL/4) + p4] = o4;
        }
    }
}

// ---------------- launch ----------------
extern "C" void kernel_launch(void* const* d_in, const int* in_sizes, int n_in,
                              void* d_out, int out_size) {
    const float* x    = (const float*)d_in[0];
    const float* c1w  = (const float*)d_in[1];
    const float* c1b  = (const float*)d_in[2];
    const float* bn1g = (const float*)d_in[3];
    const float* bn1b = (const float*)d_in[4];
    const float* c3w  = (const float*)d_in[5];
    // d_in[6] = conv3_b : cancels inside BN3, unused
    const float* bn3g = (const float*)d_in[7];
    const float* bn3b = (const float*)d_in[8];
    const float* gng  = (const float*)d_in[9];
    const float* gnb  = (const float*)d_in[10];
    float* out = (float*)d_out;

    cudaFuncSetAttribute(k_conv, cudaFuncAttributeMaxDynamicSharedMemorySize, SMEM_K3);

    k_zero<<<96, 256>>>();
    k_pool<<<dim3(128, 4), 256>>>(x);
    k_excite<<<1, 1024>>>(c1w, c1b, bn1g, bn1b);
    k_conv<<<dim3(16, 8, 16), 256, SMEM_K3>>>(x, c3w);
    k_stats<<<1, 128>>>(gng, gnb, bn3g, bn3b);
    k_x2mean<<<1024, 256>>>();
    k_soft<<<1, 32>>>(gnb);
    k_out<<<1024, 256>>>(x, out);
}